// round 12
// baseline (speedup 1.0000x reference)
#include <cuda_runtime.h>
#include <cstdint>
#include <math.h>

#define NBn 100000
#define NE  2000000
#define DD  32
#define NBD (NBn*DD)
#define FULL 0xffffffffu

// ---------------- device scratch (static, no runtime alloc) ----------------
__device__ float g_h[2][2][NBD];     // [buf][type: 0=author,1=paper]
__device__ float g_QT[2][2][NBD];    // [etype][head] qt = h_dst @ M_h
__device__ int   g_deg[2][NBn];
__device__ int   g_off[2][NBn];
__device__ int   g_cur[2][NBn];
__device__ int   g_lsrc[2][NE];
__device__ int   g_leid[2][NE];
__device__ float g_lrt[2][NE];
__device__ float g_eff[2][(size_t)NE*DD];  // CSR-ordered edge features
__device__ int   g_gcnt[2];
__device__ float g_M [2][2][1024];   // [etype][head] Wq_h @ Wk_h^T
__device__ float g_T [2][2][1024];   // [etype][head][d*32+j]  Wv_h @ lin_h
__device__ float g_ET[2][2][1024];   // elin_w @ T
__device__ float g_bT[2][2][32];     // elin_b @ T

__device__ __forceinline__ void cp_async4(unsigned int saddr, const void* gptr) {
    asm volatile("cp.async.ca.shared.global [%0], [%1], 4;" :: "r"(saddr), "l"(gptr));
}
__device__ __forceinline__ void cp_async16(unsigned int saddr, const void* gptr) {
    asm volatile("cp.async.cg.shared.global [%0], [%1], 16;" :: "r"(saddr), "l"(gptr));
}
__device__ __forceinline__ void cp_commit() {
    asm volatile("cp.async.commit_group;");
}
__device__ __forceinline__ void cp_wait0() {
    asm volatile("cp.async.wait_group 0;");
}
__device__ __forceinline__ void cp_wait1() {
    asm volatile("cp.async.wait_group 1;");
}

// ---------------- zero counters ----------------
__global__ void __launch_bounds__(256) zero_kernel() {
    int i = blockIdx.x * blockDim.x + threadIdx.x;
    if (i < NBn) {
        g_deg[0][i] = 0; g_deg[1][i] = 0;
        g_cur[0][i] = 0; g_cur[1][i] = 0;
    }
    if (i == 0) { g_gcnt[0] = 0; g_gcnt[1] = 0; }
}

// ---------------- init ----------------
__global__ void __launch_bounds__(256) init_kernel(
                            const float* __restrict__ mem_a, const float* __restrict__ mem_p,
                            const int* __restrict__ nxa, const int* __restrict__ nxp,
                            const float* __restrict__ tsa, const float* __restrict__ tsp,
                            const float* __restrict__ tw, const float* __restrict__ tb,
                            float* __restrict__ out) {
    int i = blockIdx.x * blockDim.x + threadIdx.x;
    if (i >= 2 * NBD) return;
    if (i < NBD) {
        int n = i >> 5, d = i & 31;
        float m = mem_a[(size_t)nxa[n] * DD + d];
        float te = __cosf(fmaf(tsa[n], tw[d], tb[d]));
        g_h[0][0][i] = m + te;
        out[(size_t)2 * NBD + i] = m;
    } else {
        int j = i - NBD;
        int n = j >> 5, d = j & 31;
        float m = mem_p[(size_t)nxp[n] * DD + d];
        float te = __cosf(fmaf(tsp[n], tw[d], tb[d]));
        g_h[0][1][j] = m + te;
        out[(size_t)3 * NBD + j] = m;
    }
}

// ---------------- CSR build ----------------
__global__ void __launch_bounds__(256) hist_kernel(const int* __restrict__ ei1_w,
                                                   const int* __restrict__ mask_w,
                                                   const int* __restrict__ ei1_r,
                                                   const int* __restrict__ mask_r) {
    int e = blockIdx.x * blockDim.x + threadIdx.x;
    if (e >= NE) return;
    if (mask_w[e] != 0) atomicAdd(&g_deg[0][ei1_w[e]], 1);
    if (mask_r[e] != 0) atomicAdd(&g_deg[1][ei1_r[e]], 1);
}

__global__ void __launch_bounds__(256) offs_kernel() {
    int etype = blockIdx.y;
    int n = blockIdx.x * blockDim.x + threadIdx.x;
    int lane = threadIdx.x & 31;
    int d = (n < NBn) ? g_deg[etype][n] : 0;
    int s = d;
    #pragma unroll
    for (int o = 1; o < 32; o <<= 1) {
        int t = __shfl_up_sync(FULL, s, o);
        if (lane >= o) s += t;
    }
    int tot = __shfl_sync(FULL, s, 31);
    int base = 0;
    if (lane == 31) base = atomicAdd(&g_gcnt[etype], tot);
    base = __shfl_sync(FULL, base, 31);
    if (n < NBn) g_off[etype][n] = base + s - d;
}

__global__ void __launch_bounds__(256) fill_kernel(
                            const int* __restrict__ ei_w, const int* __restrict__ eidx_w,
                            const float* __restrict__ rt_w, const int* __restrict__ mask_w,
                            const int* __restrict__ ei_r, const int* __restrict__ eidx_r,
                            const float* __restrict__ rt_r, const int* __restrict__ mask_r) {
    int e = blockIdx.x * blockDim.x + threadIdx.x;
    if (e >= NE) return;
    if (mask_w[e] != 0) {
        int dn = ei_w[NE + e];
        int pos = g_off[0][dn] + atomicAdd(&g_cur[0][dn], 1);
        g_lsrc[0][pos] = ei_w[e];
        g_leid[0][pos] = eidx_w[e];
        g_lrt[0][pos]  = rt_w[e];
    }
    if (mask_r[e] != 0) {
        int dn = ei_r[NE + e];
        int pos = g_off[1][dn] + atomicAdd(&g_cur[1][dn], 1);
        g_lsrc[1][pos] = ei_r[e];
        g_leid[1][pos] = eidx_r[e];
        g_lrt[1][pos]  = rt_r[e];
    }
}

// ---------------- CSR-ordered ef gather (once; reused by both layers) ----------------
__global__ void __launch_bounds__(256) efgather_kernel(const float* __restrict__ ef) {
    int etype = blockIdx.y;
    int gid = blockIdx.x * 256 + threadIdx.x;
    int slot = gid >> 5, lane = gid & 31;
    if (slot >= g_gcnt[etype]) return;
    int eid = g_leid[etype][slot];
    g_eff[etype][(size_t)slot * DD + lane] = ef[(size_t)eid * DD + lane];
}

// ---------------- M_h = Wq_h @ Wk_h^T ----------------
__global__ void __launch_bounds__(256) mmat_kernel(
                            const float* __restrict__ Wq_w, const float* __restrict__ Wk_w,
                            const float* __restrict__ Wq_r, const float* __restrict__ Wk_r) {
    int tid = blockIdx.x * blockDim.x + threadIdx.x;   // 4096 items
    if (tid >= 4096) return;
    int etype = tid >> 11, head = (tid >> 10) & 1, f = (tid >> 5) & 31, g = tid & 31;
    const float* Wq = etype ? Wq_r : Wq_w;
    const float* Wk = etype ? Wk_r : Wk_w;
    float acc = 0.f;
    #pragma unroll
    for (int m = 0; m < 16; m++)
        acc += Wq[f * 32 + head * 16 + m] * Wk[g * 32 + head * 16 + m];
    g_M[etype][head][f * 32 + g] = acc;
}

// ---------------- fold Wv@lin ----------------
__global__ void __launch_bounds__(256) tmat1_kernel(
                            const float* __restrict__ Wv_w, const float* __restrict__ lin_p,
                            const float* __restrict__ Wv_r, const float* __restrict__ lin_a) {
    int tid = blockIdx.x * blockDim.x + threadIdx.x;
    if (tid >= 1024) return;
    int d = tid >> 5, j = tid & 31;
    for (int t = 0; t < 2; t++) {
        const float* Wv  = t ? Wv_r  : Wv_w;
        const float* lin = t ? lin_a : lin_p;
        for (int h = 0; h < 2; h++) {
            float acc = 0.f;
            #pragma unroll
            for (int m = 0; m < 16; m++)
                acc += Wv[d * 32 + h * 16 + m] * lin[(h * 16 + m) * 32 + j];
            g_T[t][h][d * 32 + j] = acc;
        }
    }
}

__global__ void __launch_bounds__(256) tmat2_kernel(
                            const float* __restrict__ elw_w, const float* __restrict__ elb_w,
                            const float* __restrict__ elw_r, const float* __restrict__ elb_r) {
    int tid = blockIdx.x * blockDim.x + threadIdx.x;
    if (tid >= 1024) return;
    int d = tid >> 5, j = tid & 31;
    for (int t = 0; t < 2; t++) {
        const float* elw = t ? elw_r : elw_w;
        const float* elb = t ? elb_r : elb_w;
        for (int h = 0; h < 2; h++) {
            float acc = 0.f;
            #pragma unroll
            for (int k = 0; k < 32; k++)
                acc += elw[d * 32 + k] * g_T[t][h][k * 32 + j];
            g_ET[t][h][d * 32 + j] = acc;
            if (d == 0) {
                float b = 0.f;
                #pragma unroll
                for (int k = 0; k < 32; k++)
                    b += elb[k] * g_T[t][h][k * 32 + j];
                g_bT[t][h][j] = b;
            }
        }
    }
}

// ---------------- per-layer qt tables: qt_h = h_dst @ M_h ----------------
__global__ void __launch_bounds__(256) qt_kernel(int buf) {
    __shared__ float sM[1024];
    int tbl = blockIdx.y;                 // etype*2 + head
    int etype = tbl >> 1, head = tbl & 1;
    int dsttype = (etype == 0) ? 1 : 0;
    for (int i = threadIdx.x; i < 1024; i += blockDim.x) sM[i] = g_M[etype][head][i];
    __syncthreads();
    int warp = threadIdx.x >> 5, lane = threadIdx.x & 31;
    int n = blockIdx.x * 8 + warp;
    if (n >= NBn) return;
    float x = g_h[buf][dsttype][n * DD + lane];
    float acc = 0.f;
    #pragma unroll
    for (int f = 0; f < 32; f++)
        acc = fmaf(__shfl_sync(FULL, x, f), sM[f * 32 + lane], acc);
    g_QT[etype][head][n * DD + lane] = acc;
}

// ---------------- attention aggregation + fused node update ----------------
// 192 threads = 6 warps; each warp pipelines 8 nodes (double-buffered cp.async).
#define AGG_WARPS 6
#define AGG_NPW   8
#define AGG_NPB   (AGG_WARPS*AGG_NPW)
#define AGG_GB    ((NBn + AGG_NPB - 1) / AGG_NPB)
// dynamic smem: 4 weight tables (4096 f) + per-warp double-buffered X,F tiles
#define AGG_SMEM_FLOATS (4096 + AGG_WARPS*2*1024*2)
#define AGG_SMEM_BYTES  (AGG_SMEM_FLOATS*4)

__global__ void __launch_bounds__(192) agg_kernel(int inbuf, int outbuf,
                           const float* __restrict__ time_w, const float* __restrict__ time_b,
                           float* __restrict__ out, int last) {
    extern __shared__ float smem[];
    int etype = (blockIdx.x >= AGG_GB) ? 1 : 0;
    int blk = blockIdx.x - etype * AGG_GB;

    float* sT0 = smem;
    float* sT1 = smem + 1024;
    float* sE0 = smem + 2048;
    float* sE1 = smem + 3072;
    for (int i = threadIdx.x; i < 1024; i += blockDim.x) {
        sT0[i] = g_T[etype][0][i];  sT1[i] = g_T[etype][1][i];
        sE0[i] = g_ET[etype][0][i]; sE1[i] = g_ET[etype][1][i];
    }
    __syncthreads();

    int warp = threadIdx.x >> 5, lane = threadIdx.x & 31;
    float* wX = smem + 4096 + warp * 2048;                      // [buf][32][32] swizzled
    float* wF = smem + 4096 + AGG_WARPS * 2048 + warp * 2048;   // [buf][32][32] plain
    unsigned int xbase = (unsigned int)__cvta_generic_to_shared(wX);
    unsigned int fbase = (unsigned int)__cvta_generic_to_shared(wF);

    int srctype = (etype == 0) ? 0 : 1;
    int dsttype = 1 - srctype;
    const float* hsrc = g_h[inbuf][srctype];
    const float* hdst = g_h[inbuf][dsttype];
    const int*   lsrc = g_lsrc[etype];
    const float* lrt  = g_lrt[etype];
    const float* eff  = g_eff[etype];
    float tw = time_w[lane], tb = time_b[lane];
    float sbr0 = g_bT[etype][0][lane], sbr1 = g_bT[etype][1][lane];

    int n0 = blk * AGG_NPB + warp * AGG_NPW;

    // stage first batch (up to 32 edges) of node `n` into buffer `b`
    auto stage = [&](int n, int b, int& begS, int& degS, float& prtS) {
        begS = g_off[etype][n]; degS = g_deg[etype][n];
        int cnt = min(32, degS);
        int psrc = 0; float prt = 0.f;
        if (lane < cnt) { psrc = lsrc[begS + lane]; prt = lrt[begS + lane]; }
        prtS = prt;
        unsigned int xb = xbase + (b << 12);
        unsigned int fb = fbase + (b << 12);
        for (int j = 0; j < cnt; j++) {
            int srcj = __shfl_sync(FULL, psrc, j);
            cp_async4(xb + ((j * 32 + ((lane + j) & 31)) << 2),
                      hsrc + (size_t)srcj * DD + lane);
        }
        const float* fsrc = eff + (size_t)begS * DD;
        for (int q = lane; q < cnt * 8; q += 32)
            cp_async16(fb + (q << 4), fsrc + q * 4);
    };

    // prologue: prefetch node 0
    int begC = 0, degC = 0; float prtC = 0.f;
    if (n0 < NBn) stage(n0, 0, begC, degC, prtC);
    cp_commit();

    int curbuf = 0;
    for (int rep = 0; rep < AGG_NPW; rep++) {
        int n = n0 + rep;
        if (n >= NBn) break;                       // warp-uniform
        int nn = n0 + rep + 1;
        bool hasnext = (rep + 1 < AGG_NPW) && (nn < NBn);

        int begN = 0, degN = 0; float prtN = 0.f;
        if (hasnext) stage(nn, curbuf ^ 1, begN, degN, prtN);
        cp_commit();
        if (hasnext) cp_wait1(); else cp_wait0();
        __syncwarp();

        float qt0 = g_QT[etype][0][n * DD + lane];
        float qt1 = g_QT[etype][1][n * DD + lane];

        float u0 = 0.f, u1 = 0.f, e0 = 0.f, e1 = 0.f, den0 = 0.f, den1 = 0.f;
        float m0 = -1e30f, m1 = -1e30f;

        float* Xb = wX + (curbuf << 10);
        float* Fb = wF + (curbuf << 10);

        auto compute_batch = [&](int cnt, float prt) {
            bool valid = lane < cnt;
            float a0 = 0.f, a1 = 0.f;
            #pragma unroll
            for (int d = 0; d < 32; d++) {
                float xd = Xb[lane * 32 + ((d + lane) & 31)];
                a0 = fmaf(xd, __shfl_sync(FULL, qt0, d), a0);
                a1 = fmaf(xd, __shfl_sync(FULL, qt1, d), a1);
            }
            float s0 = valid ? a0 * 0.25f : -1e30f;
            float s1 = valid ? a1 * 0.25f : -1e30f;
            float bm0 = s0, bm1 = s1;
            #pragma unroll
            for (int o = 16; o > 0; o >>= 1) {
                bm0 = fmaxf(bm0, __shfl_xor_sync(FULL, bm0, o));
                bm1 = fmaxf(bm1, __shfl_xor_sync(FULL, bm1, o));
            }
            float nm0 = fmaxf(m0, bm0), nm1 = fmaxf(m1, bm1);
            float sc0 = __expf(m0 - nm0), sc1 = __expf(m1 - nm1);
            u0 *= sc0; e0 *= sc0; den0 *= sc0; m0 = nm0;
            u1 *= sc1; e1 *= sc1; den1 *= sc1; m1 = nm1;
            float p0 = valid ? __expf(s0 - m0) : 0.f;
            float p1 = valid ? __expf(s1 - m1) : 0.f;
            float d0 = p0, d1 = p1;
            #pragma unroll
            for (int o = 16; o > 0; o >>= 1) {
                d0 += __shfl_xor_sync(FULL, d0, o);
                d1 += __shfl_xor_sync(FULL, d1, o);
            }
            den0 += d0; den1 += d1;
            for (int j = 0; j < cnt; j++) {
                float pj0 = __shfl_sync(FULL, p0, j);
                float pj1 = __shfl_sync(FULL, p1, j);
                float rt  = __shfl_sync(FULL, prt, j);
                float x = Xb[j * 32 + ((lane + j) & 31)] + __cosf(fmaf(rt, tw, tb));
                float fe = Fb[j * 32 + lane];
                u0 = fmaf(pj0, x, u0); u1 = fmaf(pj1, x, u1);
                e0 = fmaf(pj0, fe, e0); e1 = fmaf(pj1, fe, e1);
            }
        };

        compute_batch(min(32, degC), prtC);

        // rare spill batches (deg > 32): synchronous staging into current buffer
        for (int base = 32; base < degC; base += 32) {
            __syncwarp();
            int cnt = min(32, degC - base);
            int idx = begC + base + lane;
            int psrc = 0; float prt = 0.f;
            if (lane < cnt) { psrc = lsrc[idx]; prt = lrt[idx]; }
            unsigned int xb = xbase + (curbuf << 12);
            unsigned int fb = fbase + (curbuf << 12);
            for (int j = 0; j < cnt; j++) {
                int srcj = __shfl_sync(FULL, psrc, j);
                cp_async4(xb + ((j * 32 + ((lane + j) & 31)) << 2),
                          hsrc + (size_t)srcj * DD + lane);
            }
            const float* fsrc = eff + (size_t)(begC + base) * DD;
            for (int q = lane; q < cnt * 8; q += 32)
                cp_async16(fb + (q << 4), fsrc + q * 4);
            cp_commit();
            cp_wait0();
            __syncwarp();
            compute_batch(cnt, prt);
        }

        float inv0 = 1.f / (den0 + 1e-9f), inv1 = 1.f / (den1 + 1e-9f);
        float bs0 = den0 * inv0, bs1 = den1 * inv1;
        float xa0 = u0 * inv0, xa1 = u1 * inv1, ga0 = e0 * inv0, ga1 = e1 * inv1;

        float acc = bs0 * sbr0 + bs1 * sbr1;
        #pragma unroll
        for (int d = 0; d < 32; d++) {
            float a0 = __shfl_sync(FULL, xa0, d);
            float a1 = __shfl_sync(FULL, xa1, d);
            float b0 = __shfl_sync(FULL, ga0, d);
            float b1 = __shfl_sync(FULL, ga1, d);
            acc = fmaf(a0, sT0[d * 32 + lane], acc);
            acc = fmaf(a1, sT1[d * 32 + lane], acc);
            acc = fmaf(b0, sE0[d * 32 + lane], acc);
            acc = fmaf(b1, sE1[d * 32 + lane], acc);
        }
        float r = fmaxf(acc, 0.f) + hdst[n * DD + lane];
        g_h[outbuf][dsttype][n * DD + lane] = r;
        if (last) out[(size_t)dsttype * NBD + n * DD + lane] = r;

        begC = begN; degC = degN; prtC = prtN;
        curbuf ^= 1;
        __syncwarp();
    }
}

// ---------------- launch ----------------
extern "C" void kernel_launch(void* const* d_in, const int* in_sizes, int n_in,
                              void* d_out, int out_size) {
    const float* mem_a   = (const float*)d_in[0];
    const float* mem_p   = (const float*)d_in[1];
    const float* ef      = (const float*)d_in[2];
    const int*   nxa     = (const int*)  d_in[3];
    const int*   nxp     = (const int*)  d_in[4];
    const float* tsa     = (const float*)d_in[5];
    const float* tsp     = (const float*)d_in[6];
    const int*   ei_w    = (const int*)  d_in[7];
    const float* rt_w    = (const float*)d_in[8];
    const int*   eidx_w  = (const int*)  d_in[9];
    const int*   mask_w  = (const int*)  d_in[10];
    const int*   ei_r    = (const int*)  d_in[11];
    const float* rt_r    = (const float*)d_in[12];
    const int*   eidx_r  = (const int*)  d_in[13];
    const int*   mask_r  = (const int*)  d_in[14];
    const float* tw      = (const float*)d_in[15];
    const float* tb      = (const float*)d_in[16];
    const float* Wk_w    = (const float*)d_in[17];
    const float* Wq_w    = (const float*)d_in[18];
    const float* Wv_w    = (const float*)d_in[19];
    const float* elw_w   = (const float*)d_in[20];
    const float* elb_w   = (const float*)d_in[21];
    const float* Wk_r    = (const float*)d_in[22];
    const float* Wq_r    = (const float*)d_in[23];
    const float* Wv_r    = (const float*)d_in[24];
    const float* elw_r   = (const float*)d_in[25];
    const float* elb_r   = (const float*)d_in[26];
    const float* lin_a   = (const float*)d_in[27];
    const float* lin_p   = (const float*)d_in[28];
    float* out = (float*)d_out;

    static int smem_set = 0;
    if (!smem_set) {
        cudaFuncSetAttribute(agg_kernel, cudaFuncAttributeMaxDynamicSharedMemorySize,
                             AGG_SMEM_BYTES);
        smem_set = 1;
    }

    zero_kernel<<<(NBn + 255) / 256, 256>>>();
    init_kernel<<<(2 * NBD + 255) / 256, 256>>>(mem_a, mem_p, nxa, nxp, tsa, tsp, tw, tb, out);

    int egrid = (NE + 255) / 256;
    hist_kernel<<<egrid, 256>>>(ei_w + NE, mask_w, ei_r + NE, mask_r);
    offs_kernel<<<dim3((NBn + 255) / 256, 2), 256>>>();
    fill_kernel<<<egrid, 256>>>(ei_w, eidx_w, rt_w, mask_w, ei_r, eidx_r, rt_r, mask_r);
    efgather_kernel<<<dim3(NE * 32 / 256, 2), 256>>>(ef);

    mmat_kernel<<<16, 256>>>(Wq_w, Wk_w, Wq_r, Wk_r);
    tmat1_kernel<<<4, 256>>>(Wv_w, lin_p, Wv_r, lin_a);
    tmat2_kernel<<<4, 256>>>(elw_w, elb_w, elw_r, elb_r);

    int buf = 0;
    for (int layer = 0; layer < 2; layer++) {
        qt_kernel<<<dim3(12500, 4), 256>>>(buf);
        agg_kernel<<<2 * AGG_GB, 192, AGG_SMEM_BYTES>>>(buf, buf ^ 1, tw, tb, out, layer == 1);
        buf ^= 1;
    }
}

// round 15
// speedup vs baseline: 1.6215x; 1.6215x over previous
#include <cuda_runtime.h>
#include <cstdint>
#include <math.h>

#define NBn 100000
#define NE  2000000
#define DD  32
#define NBD (NBn*DD)
#define FULL 0xffffffffu

// ---------------- device scratch (static, no runtime alloc) ----------------
__device__ float g_h[2][2][NBD];     // [buf][type: 0=author,1=paper]
__device__ float g_QT[2][2][NBD];    // [etype][head] qt = h_dst @ M_h
__device__ int   g_deg[2][NBn];
__device__ int   g_off[2][NBn];
__device__ int   g_cur[2][NBn];
__device__ int   g_lsrc[2][NE];
__device__ int   g_leid[2][NE];
__device__ float g_lrt[2][NE];
__device__ int   g_gcnt[2];
__device__ float g_M [2][2][1024];   // [etype][head] Wq_h @ Wk_h^T
__device__ float g_T [2][2][1024];   // [etype][head][d*32+j]  Wv_h @ lin_h
__device__ float g_ET[2][2][1024];   // elin_w @ T
__device__ float g_bT[2][2][32];     // elin_b @ T

__device__ __forceinline__ void cp_async16(unsigned int saddr, const void* gptr) {
    asm volatile("cp.async.cg.shared.global [%0], [%1], 16;" :: "r"(saddr), "l"(gptr));
}
__device__ __forceinline__ void cp_commit() { asm volatile("cp.async.commit_group;"); }
__device__ __forceinline__ void cp_wait0()  { asm volatile("cp.async.wait_group 0;"); }

// ---------------- zero counters ----------------
__global__ void __launch_bounds__(256) zero_kernel() {
    int i = blockIdx.x * blockDim.x + threadIdx.x;
    if (i < NBn) {
        g_deg[0][i] = 0; g_deg[1][i] = 0;
        g_cur[0][i] = 0; g_cur[1][i] = 0;
    }
    if (i == 0) { g_gcnt[0] = 0; g_gcnt[1] = 0; }
}

// ---------------- init ----------------
__global__ void __launch_bounds__(256) init_kernel(
                            const float* __restrict__ mem_a, const float* __restrict__ mem_p,
                            const int* __restrict__ nxa, const int* __restrict__ nxp,
                            const float* __restrict__ tsa, const float* __restrict__ tsp,
                            const float* __restrict__ tw, const float* __restrict__ tb,
                            float* __restrict__ out) {
    int i = blockIdx.x * blockDim.x + threadIdx.x;
    if (i >= 2 * NBD) return;
    if (i < NBD) {
        int n = i >> 5, d = i & 31;
        float m = mem_a[(size_t)nxa[n] * DD + d];
        float te = __cosf(fmaf(tsa[n], tw[d], tb[d]));
        g_h[0][0][i] = m + te;
        out[(size_t)2 * NBD + i] = m;
    } else {
        int j = i - NBD;
        int n = j >> 5, d = j & 31;
        float m = mem_p[(size_t)nxp[n] * DD + d];
        float te = __cosf(fmaf(tsp[n], tw[d], tb[d]));
        g_h[0][1][j] = m + te;
        out[(size_t)3 * NBD + j] = m;
    }
}

// ---------------- CSR build ----------------
__global__ void __launch_bounds__(256) hist_kernel(const int* __restrict__ ei1_w,
                                                   const int* __restrict__ mask_w,
                                                   const int* __restrict__ ei1_r,
                                                   const int* __restrict__ mask_r) {
    int e = blockIdx.x * blockDim.x + threadIdx.x;
    if (e >= NE) return;
    if (mask_w[e] != 0) atomicAdd(&g_deg[0][ei1_w[e]], 1);
    if (mask_r[e] != 0) atomicAdd(&g_deg[1][ei1_r[e]], 1);
}

__global__ void __launch_bounds__(256) offs_kernel() {
    int etype = blockIdx.y;
    int n = blockIdx.x * blockDim.x + threadIdx.x;
    int lane = threadIdx.x & 31;
    int d = (n < NBn) ? g_deg[etype][n] : 0;
    int s = d;
    #pragma unroll
    for (int o = 1; o < 32; o <<= 1) {
        int t = __shfl_up_sync(FULL, s, o);
        if (lane >= o) s += t;
    }
    int tot = __shfl_sync(FULL, s, 31);
    int base = 0;
    if (lane == 31) base = atomicAdd(&g_gcnt[etype], tot);
    base = __shfl_sync(FULL, base, 31);
    if (n < NBn) g_off[etype][n] = base + s - d;
}

__global__ void __launch_bounds__(256) fill_kernel(
                            const int* __restrict__ ei_w, const int* __restrict__ eidx_w,
                            const float* __restrict__ rt_w, const int* __restrict__ mask_w,
                            const int* __restrict__ ei_r, const int* __restrict__ eidx_r,
                            const float* __restrict__ rt_r, const int* __restrict__ mask_r) {
    int e = blockIdx.x * blockDim.x + threadIdx.x;
    if (e >= NE) return;
    if (mask_w[e] != 0) {
        int dn = ei_w[NE + e];
        int pos = g_off[0][dn] + atomicAdd(&g_cur[0][dn], 1);
        g_lsrc[0][pos] = ei_w[e];
        g_leid[0][pos] = eidx_w[e];
        g_lrt[0][pos]  = rt_w[e];
    }
    if (mask_r[e] != 0) {
        int dn = ei_r[NE + e];
        int pos = g_off[1][dn] + atomicAdd(&g_cur[1][dn], 1);
        g_lsrc[1][pos] = ei_r[e];
        g_leid[1][pos] = eidx_r[e];
        g_lrt[1][pos]  = rt_r[e];
    }
}

// ---------------- M_h = Wq_h @ Wk_h^T ----------------
__global__ void __launch_bounds__(256) mmat_kernel(
                            const float* __restrict__ Wq_w, const float* __restrict__ Wk_w,
                            const float* __restrict__ Wq_r, const float* __restrict__ Wk_r) {
    int tid = blockIdx.x * blockDim.x + threadIdx.x;   // 4096 items
    if (tid >= 4096) return;
    int etype = tid >> 11, head = (tid >> 10) & 1, f = (tid >> 5) & 31, g = tid & 31;
    const float* Wq = etype ? Wq_r : Wq_w;
    const float* Wk = etype ? Wk_r : Wk_w;
    float acc = 0.f;
    #pragma unroll
    for (int m = 0; m < 16; m++)
        acc += Wq[f * 32 + head * 16 + m] * Wk[g * 32 + head * 16 + m];
    g_M[etype][head][f * 32 + g] = acc;
}

// ---------------- fold Wv@lin ----------------
__global__ void __launch_bounds__(256) tmat1_kernel(
                            const float* __restrict__ Wv_w, const float* __restrict__ lin_p,
                            const float* __restrict__ Wv_r, const float* __restrict__ lin_a) {
    int tid = blockIdx.x * blockDim.x + threadIdx.x;
    if (tid >= 1024) return;
    int d = tid >> 5, j = tid & 31;
    for (int t = 0; t < 2; t++) {
        const float* Wv  = t ? Wv_r  : Wv_w;
        const float* lin = t ? lin_a : lin_p;
        for (int h = 0; h < 2; h++) {
            float acc = 0.f;
            #pragma unroll
            for (int m = 0; m < 16; m++)
                acc += Wv[d * 32 + h * 16 + m] * lin[(h * 16 + m) * 32 + j];
            g_T[t][h][d * 32 + j] = acc;
        }
    }
}

__global__ void __launch_bounds__(256) tmat2_kernel(
                            const float* __restrict__ elw_w, const float* __restrict__ elb_w,
                            const float* __restrict__ elw_r, const float* __restrict__ elb_r) {
    int tid = blockIdx.x * blockDim.x + threadIdx.x;
    if (tid >= 1024) return;
    int d = tid >> 5, j = tid & 31;
    for (int t = 0; t < 2; t++) {
        const float* elw = t ? elw_r : elw_w;
        const float* elb = t ? elb_r : elb_w;
        for (int h = 0; h < 2; h++) {
            float acc = 0.f;
            #pragma unroll
            for (int k = 0; k < 32; k++)
                acc += elw[d * 32 + k] * g_T[t][h][k * 32 + j];
            g_ET[t][h][d * 32 + j] = acc;
            if (d == 0) {
                float b = 0.f;
                #pragma unroll
                for (int k = 0; k < 32; k++)
                    b += elb[k] * g_T[t][h][k * 32 + j];
                g_bT[t][h][j] = b;
            }
        }
    }
}

// ---------------- per-layer qt tables: qt_h = h_dst @ M_h ----------------
__global__ void __launch_bounds__(256) qt_kernel(int buf) {
    __shared__ float sM[1024];
    int tbl = blockIdx.y;                 // etype*2 + head
    int etype = tbl >> 1, head = tbl & 1;
    int dsttype = (etype == 0) ? 1 : 0;
    for (int i = threadIdx.x; i < 1024; i += blockDim.x) sM[i] = g_M[etype][head][i];
    __syncthreads();
    int warp = threadIdx.x >> 5, lane = threadIdx.x & 31;
    int n = blockIdx.x * 8 + warp;
    if (n >= NBn) return;
    float x = g_h[buf][dsttype][n * DD + lane];
    float acc = 0.f;
    #pragma unroll
    for (int f = 0; f < 32; f++)
        acc = fmaf(__shfl_sync(FULL, x, f), sM[f * 32 + lane], acc);
    g_QT[etype][head][n * DD + lane] = acc;
}

// ---------------- attention aggregation + fused node update ----------------
// 192 threads = 6 warps; each warp processes 8 nodes.
// X tile layout: row j stride 32 floats; element d at
//   j*32 + ((((d>>2)^(j&7))<<2) | (d&3))      (16B-granular XOR swizzle)
// F tile: plain row-major [j][lane].
#define AGG_WARPS 6
#define AGG_NPW   8
#define AGG_NPB   (AGG_WARPS*AGG_NPW)
#define AGG_GB    ((NBn + AGG_NPB - 1) / AGG_NPB)
__global__ void __launch_bounds__(192) agg_kernel(int inbuf, int outbuf,
                           const float* __restrict__ ef_table,
                           const float* __restrict__ time_w, const float* __restrict__ time_b,
                           float* __restrict__ out, int last) {
    int etype = (blockIdx.x >= AGG_GB) ? 1 : 0;
    int blk = blockIdx.x - etype * AGG_GB;

    __shared__ float sT0[1024], sT1[1024], sE0[1024], sE1[1024];
    __shared__ float sX[AGG_WARPS][1024];
    __shared__ float sF[AGG_WARPS][1024];
    for (int i = threadIdx.x; i < 1024; i += blockDim.x) {
        sT0[i] = g_T[etype][0][i];  sT1[i] = g_T[etype][1][i];
        sE0[i] = g_ET[etype][0][i]; sE1[i] = g_ET[etype][1][i];
    }
    __syncthreads();

    int warp = threadIdx.x >> 5, lane = threadIdx.x & 31;
    int srctype = (etype == 0) ? 0 : 1;
    int dsttype = 1 - srctype;
    const float* hsrc = g_h[inbuf][srctype];
    const float* hdst = g_h[inbuf][dsttype];
    const int*   lsrc = g_lsrc[etype];
    const int*   leid = g_leid[etype];
    const float* lrt  = g_lrt[etype];
    float tw = time_w[lane], tb = time_b[lane];
    float sbr0 = g_bT[etype][0][lane], sbr1 = g_bT[etype][1][lane];
    float* X  = sX[warp];
    float* Fe = sF[warp];
    unsigned int xbase = (unsigned int)__cvta_generic_to_shared(X);
    unsigned int fbase = (unsigned int)__cvta_generic_to_shared(Fe);

    int rsub  = lane >> 3;      // row-within-group for vector staging
    int chunk = lane & 7;       // 16B chunk index
    int laneSw = lane & 7;      // dot-pass swizzle term
    int laneHi = lane >> 2, laneLo = lane & 3;  // accum-pass index terms

    for (int rep = 0; rep < AGG_NPW; rep++) {
        int n = blk * AGG_NPB + warp * AGG_NPW + rep;
        if (n >= NBn) break;                        // warp-uniform

        float qt0 = g_QT[etype][0][n * DD + lane];
        float qt1 = g_QT[etype][1][n * DD + lane];
        int beg = g_off[etype][n], deg = g_deg[etype][n];

        float u0 = 0.f, u1 = 0.f, e0 = 0.f, e1 = 0.f, den0 = 0.f, den1 = 0.f;
        float m0 = -1e30f, m1 = -1e30f;

        for (int base = 0; base < deg; base += 32) {
            int cnt = min(32, deg - base);
            int idx = beg + base + lane;
            bool valid = lane < cnt;
            int psrc = 0, peid = 0; float prt = 0.f;
            if (valid) { psrc = lsrc[idx]; peid = leid[idx]; prt = lrt[idx]; }

            // vectorized stage: 4 rows per LDGSTS.128; defaults (0) keep OOB rows safe
            for (int g = 0; g * 4 < cnt; g++) {
                int j = g * 4 + rsub;
                int srcj = __shfl_sync(FULL, psrc, j);
                int eidj = __shfl_sync(FULL, peid, j);
                cp_async16(xbase + (unsigned)(j * 128 + (((chunk ^ (j & 7)) << 4))),
                           hsrc + (size_t)srcj * DD + chunk * 4);
                cp_async16(fbase + (unsigned)(j * 128 + (chunk << 4)),
                           ef_table + (size_t)eidj * DD + chunk * 4);
            }
            cp_commit();
            cp_wait0();
            __syncwarp();

            // dot: lane = edge row; 4-way LDS conflict accepted
            float a0 = 0.f, a1 = 0.f;
            #pragma unroll
            for (int d = 0; d < 32; d++) {
                float xd = X[lane * 32 + ((((d >> 2) ^ laneSw) << 2) | (d & 3))];
                a0 = fmaf(xd, __shfl_sync(FULL, qt0, d), a0);
                a1 = fmaf(xd, __shfl_sync(FULL, qt1, d), a1);
            }
            float s0 = valid ? a0 * 0.25f : -1e30f;
            float s1 = valid ? a1 * 0.25f : -1e30f;

            // batch max + rescale (once per 32 edges)
            float bm0 = s0, bm1 = s1;
            #pragma unroll
            for (int o = 16; o > 0; o >>= 1) {
                bm0 = fmaxf(bm0, __shfl_xor_sync(FULL, bm0, o));
                bm1 = fmaxf(bm1, __shfl_xor_sync(FULL, bm1, o));
            }
            float nm0 = fmaxf(m0, bm0), nm1 = fmaxf(m1, bm1);
            float sc0 = __expf(m0 - nm0), sc1 = __expf(m1 - nm1);
            u0 *= sc0; e0 *= sc0; den0 *= sc0; m0 = nm0;
            u1 *= sc1; e1 *= sc1; den1 *= sc1; m1 = nm1;
            float p0 = valid ? __expf(s0 - m0) : 0.f;
            float p1 = valid ? __expf(s1 - m1) : 0.f;
            float d0 = p0, d1 = p1;
            #pragma unroll
            for (int o = 16; o > 0; o >>= 1) {
                d0 += __shfl_xor_sync(FULL, d0, o);
                d1 += __shfl_xor_sync(FULL, d1, o);
            }
            den0 += d0; den1 += d1;

            // accumulation pass: lane = dim; conflict-free reads
            for (int j = 0; j < cnt; j++) {
                float pj0 = __shfl_sync(FULL, p0, j);
                float pj1 = __shfl_sync(FULL, p1, j);
                float rt  = __shfl_sync(FULL, prt, j);
                float x = X[j * 32 + (((laneHi ^ (j & 7)) << 2) | laneLo)]
                          + __cosf(fmaf(rt, tw, tb));
                float fe = Fe[j * 32 + lane];
                u0 = fmaf(pj0, x, u0); u1 = fmaf(pj1, x, u1);
                e0 = fmaf(pj0, fe, e0); e1 = fmaf(pj1, fe, e1);
            }
            __syncwarp();
        }

        float inv0 = 1.f / (den0 + 1e-9f), inv1 = 1.f / (den1 + 1e-9f);
        float bs0 = den0 * inv0, bs1 = den1 * inv1;
        float xa0 = u0 * inv0, xa1 = u1 * inv1, ga0 = e0 * inv0, ga1 = e1 * inv1;

        float acc = bs0 * sbr0 + bs1 * sbr1;
        #pragma unroll
        for (int d = 0; d < 32; d++) {
            float a0 = __shfl_sync(FULL, xa0, d);
            float a1 = __shfl_sync(FULL, xa1, d);
            float b0 = __shfl_sync(FULL, ga0, d);
            float b1 = __shfl_sync(FULL, ga1, d);
            acc = fmaf(a0, sT0[d * 32 + lane], acc);
            acc = fmaf(a1, sT1[d * 32 + lane], acc);
            acc = fmaf(b0, sE0[d * 32 + lane], acc);
            acc = fmaf(b1, sE1[d * 32 + lane], acc);
        }
        float r = fmaxf(acc, 0.f) + hdst[n * DD + lane];
        g_h[outbuf][dsttype][n * DD + lane] = r;
        if (last) out[(size_t)dsttype * NBD + n * DD + lane] = r;
    }
}

// ---------------- launch ----------------
extern "C" void kernel_launch(void* const* d_in, const int* in_sizes, int n_in,
                              void* d_out, int out_size) {
    const float* mem_a   = (const float*)d_in[0];
    const float* mem_p   = (const float*)d_in[1];
    const float* ef      = (const float*)d_in[2];
    const int*   nxa     = (const int*)  d_in[3];
    const int*   nxp     = (const int*)  d_in[4];
    const float* tsa     = (const float*)d_in[5];
    const float* tsp     = (const float*)d_in[6];
    const int*   ei_w    = (const int*)  d_in[7];
    const float* rt_w    = (const float*)d_in[8];
    const int*   eidx_w  = (const int*)  d_in[9];
    const int*   mask_w  = (const int*)  d_in[10];
    const int*   ei_r    = (const int*)  d_in[11];
    const float* rt_r    = (const float*)d_in[12];
    const int*   eidx_r  = (const int*)  d_in[13];
    const int*   mask_r  = (const int*)  d_in[14];
    const float* tw      = (const float*)d_in[15];
    const float* tb      = (const float*)d_in[16];
    const float* Wk_w    = (const float*)d_in[17];
    const float* Wq_w    = (const float*)d_in[18];
    const float* Wv_w    = (const float*)d_in[19];
    const float* elw_w   = (const float*)d_in[20];
    const float* elb_w   = (const float*)d_in[21];
    const float* Wk_r    = (const float*)d_in[22];
    const float* Wq_r    = (const float*)d_in[23];
    const float* Wv_r    = (const float*)d_in[24];
    const float* elw_r   = (const float*)d_in[25];
    const float* elb_r   = (const float*)d_in[26];
    const float* lin_a   = (const float*)d_in[27];
    const float* lin_p   = (const float*)d_in[28];
    float* out = (float*)d_out;

    zero_kernel<<<(NBn + 255) / 256, 256>>>();
    init_kernel<<<(2 * NBD + 255) / 256, 256>>>(mem_a, mem_p, nxa, nxp, tsa, tsp, tw, tb, out);

    int egrid = (NE + 255) / 256;
    hist_kernel<<<egrid, 256>>>(ei_w + NE, mask_w, ei_r + NE, mask_r);
    offs_kernel<<<dim3((NBn + 255) / 256, 2), 256>>>();
    fill_kernel<<<egrid, 256>>>(ei_w, eidx_w, rt_w, mask_w, ei_r, eidx_r, rt_r, mask_r);

    mmat_kernel<<<16, 256>>>(Wq_w, Wk_w, Wq_r, Wk_r);
    tmat1_kernel<<<4, 256>>>(Wv_w, lin_p, Wv_r, lin_a);
    tmat2_kernel<<<4, 256>>>(elw_w, elb_w, elw_r, elb_r);

    int buf = 0;
    for (int layer = 0; layer < 2; layer++) {
        qt_kernel<<<dim3(12500, 4), 256>>>(buf);
        agg_kernel<<<2 * AGG_GB, 192>>>(buf, buf ^ 1, ef, tw, tb, out, layer == 1);
        buf ^= 1;
    }
}

// round 16
// speedup vs baseline: 1.7866x; 1.1018x over previous
#include <cuda_runtime.h>
#include <cstdint>
#include <math.h>

#define NBn 100000
#define NE  2000000
#define DD  32
#define NBD (NBn*DD)
#define FULL 0xffffffffu

// ---------------- device scratch (static, no runtime alloc) ----------------
__device__ float g_h[2][2][NBD];     // [buf][type: 0=author,1=paper]
__device__ int   g_deg[2][NBn];
__device__ int   g_off[2][NBn];
__device__ int   g_cur[2][NBn];
__device__ int   g_lsrc[2][NE];
__device__ int   g_leid[2][NE];
__device__ float g_lrt[2][NE];
__device__ int   g_gcnt[2];
__device__ float g_M [2][2][1024];   // [etype][head] Wq_h @ Wk_h^T
__device__ float g_T [2][2][1024];   // [etype][head][d*32+j]  Wv_h @ lin_h
__device__ float g_ET[2][2][1024];   // elin_w @ T
__device__ float g_bT[2][2][32];     // elin_b @ T

__device__ __forceinline__ void cp_async16(unsigned int saddr, const void* gptr) {
    asm volatile("cp.async.cg.shared.global [%0], [%1], 16;" :: "r"(saddr), "l"(gptr));
}
__device__ __forceinline__ void cp_commit() { asm volatile("cp.async.commit_group;"); }
__device__ __forceinline__ void cp_wait0()  { asm volatile("cp.async.wait_group 0;"); }

// ---------------- zero counters ----------------
__global__ void __launch_bounds__(256) zero_kernel() {
    int i = blockIdx.x * blockDim.x + threadIdx.x;
    if (i < NBn) {
        g_deg[0][i] = 0; g_deg[1][i] = 0;
        g_cur[0][i] = 0; g_cur[1][i] = 0;
    }
    if (i == 0) { g_gcnt[0] = 0; g_gcnt[1] = 0; }
}

// ---------------- CSR build ----------------
__global__ void __launch_bounds__(256) hist_kernel(const int* __restrict__ ei1_w,
                                                   const int* __restrict__ mask_w,
                                                   const int* __restrict__ ei1_r,
                                                   const int* __restrict__ mask_r) {
    int e = blockIdx.x * blockDim.x + threadIdx.x;
    if (e >= NE) return;
    if (mask_w[e] != 0) atomicAdd(&g_deg[0][ei1_w[e]], 1);
    if (mask_r[e] != 0) atomicAdd(&g_deg[1][ei1_r[e]], 1);
}

__global__ void __launch_bounds__(256) offs_kernel() {
    int etype = blockIdx.y;
    int n = blockIdx.x * blockDim.x + threadIdx.x;
    int lane = threadIdx.x & 31;
    int d = (n < NBn) ? g_deg[etype][n] : 0;
    int s = d;
    #pragma unroll
    for (int o = 1; o < 32; o <<= 1) {
        int t = __shfl_up_sync(FULL, s, o);
        if (lane >= o) s += t;
    }
    int tot = __shfl_sync(FULL, s, 31);
    int base = 0;
    if (lane == 31) base = atomicAdd(&g_gcnt[etype], tot);
    base = __shfl_sync(FULL, base, 31);
    if (n < NBn) g_off[etype][n] = base + s - d;
}

__global__ void __launch_bounds__(256) fill_kernel(
                            const int* __restrict__ ei_w, const int* __restrict__ eidx_w,
                            const float* __restrict__ rt_w, const int* __restrict__ mask_w,
                            const int* __restrict__ ei_r, const int* __restrict__ eidx_r,
                            const float* __restrict__ rt_r, const int* __restrict__ mask_r) {
    int e = blockIdx.x * blockDim.x + threadIdx.x;
    if (e >= NE) return;
    if (mask_w[e] != 0) {
        int dn = ei_w[NE + e];
        int pos = g_off[0][dn] + atomicAdd(&g_cur[0][dn], 1);
        g_lsrc[0][pos] = ei_w[e];
        g_leid[0][pos] = eidx_w[e];
        g_lrt[0][pos]  = rt_w[e];
    }
    if (mask_r[e] != 0) {
        int dn = ei_r[NE + e];
        int pos = g_off[1][dn] + atomicAdd(&g_cur[1][dn], 1);
        g_lsrc[1][pos] = ei_r[e];
        g_leid[1][pos] = eidx_r[e];
        g_lrt[1][pos]  = rt_r[e];
    }
}

// ---------------- prep: init h (+mem out) in blocks 0..INIT_B-1; weight folding in last block
#define INIT_B ((2*NBD + 255) / 256)
__global__ void __launch_bounds__(256) prep_kernel(
                            const float* __restrict__ mem_a, const float* __restrict__ mem_p,
                            const int* __restrict__ nxa, const int* __restrict__ nxp,
                            const float* __restrict__ tsa, const float* __restrict__ tsp,
                            const float* __restrict__ tw, const float* __restrict__ tb,
                            const float* __restrict__ Wq_w, const float* __restrict__ Wk_w,
                            const float* __restrict__ Wq_r, const float* __restrict__ Wk_r,
                            const float* __restrict__ Wv_w, const float* __restrict__ lin_p,
                            const float* __restrict__ Wv_r, const float* __restrict__ lin_a,
                            const float* __restrict__ elw_w, const float* __restrict__ elb_w,
                            const float* __restrict__ elw_r, const float* __restrict__ elb_r,
                            float* __restrict__ out) {
    if (blockIdx.x < INIT_B) {
        int i = blockIdx.x * 256 + threadIdx.x;
        if (i >= 2 * NBD) return;
        if (i < NBD) {
            int n = i >> 5, d = i & 31;
            float m = mem_a[(size_t)nxa[n] * DD + d];
            float te = __cosf(fmaf(tsa[n], tw[d], tb[d]));
            g_h[0][0][i] = m + te;
            out[(size_t)2 * NBD + i] = m;
        } else {
            int j = i - NBD;
            int n = j >> 5, d = j & 31;
            float m = mem_p[(size_t)nxp[n] * DD + d];
            float te = __cosf(fmaf(tsp[n], tw[d], tb[d]));
            g_h[0][1][j] = m + te;
            out[(size_t)3 * NBD + j] = m;
        }
        return;
    }
    // ---- const block: M, T, ET, bT ----
    __shared__ float sT[4096];
    int tid = threadIdx.x;
    for (int it = tid; it < 4096; it += 256) {    // M = Wq_h @ Wk_h^T
        int etype = it >> 11, head = (it >> 10) & 1, f = (it >> 5) & 31, g = it & 31;
        const float* Wq = etype ? Wq_r : Wq_w;
        const float* Wk = etype ? Wk_r : Wk_w;
        float acc = 0.f;
        #pragma unroll
        for (int m = 0; m < 16; m++)
            acc += Wq[f * 32 + head * 16 + m] * Wk[g * 32 + head * 16 + m];
        g_M[etype][head][f * 32 + g] = acc;
    }
    for (int it = tid; it < 4096; it += 256) {    // T = Wv_h @ lin
        int t = it >> 11, h = (it >> 10) & 1, d = (it >> 5) & 31, j = it & 31;
        const float* Wv  = t ? Wv_r  : Wv_w;
        const float* lin = t ? lin_a : lin_p;
        float acc = 0.f;
        #pragma unroll
        for (int m = 0; m < 16; m++)
            acc += Wv[d * 32 + h * 16 + m] * lin[(h * 16 + m) * 32 + j];
        sT[it] = acc;
        g_T[t][h][d * 32 + j] = acc;
    }
    __syncthreads();
    for (int it = tid; it < 4096; it += 256) {    // ET = elw @ T
        int t = it >> 11, h = (it >> 10) & 1, d = (it >> 5) & 31, j = it & 31;
        const float* elw = t ? elw_r : elw_w;
        const float* Tb = sT + t * 2048 + h * 1024;
        float acc = 0.f;
        #pragma unroll
        for (int k = 0; k < 32; k++)
            acc += elw[d * 32 + k] * Tb[k * 32 + j];
        g_ET[t][h][d * 32 + j] = acc;
    }
    for (int it = tid; it < 128; it += 256) {     // bT = elb @ T
        int t = it >> 6, h = (it >> 5) & 1, j = it & 31;
        const float* elb = t ? elb_r : elb_w;
        const float* Tb = sT + t * 2048 + h * 1024;
        float acc = 0.f;
        #pragma unroll
        for (int k = 0; k < 32; k++)
            acc += elb[k] * Tb[k * 32 + j];
        g_bT[t][h][j] = acc;
    }
}

// ---------------- attention aggregation + fused qt + node update ----------------
// 192 threads = 6 warps; each warp processes 8 nodes.
// X tile: row j stride 32; element d at j*32 + ((((d>>2)^(j&7))<<2)|(d&3)).
// F tile: plain [j][lane]. Epilogue weights via __ldg (L1-resident).
#define AGG_WARPS 6
#define AGG_NPW   8
#define AGG_NPB   (AGG_WARPS*AGG_NPW)
#define AGG_GB    ((NBn + AGG_NPB - 1) / AGG_NPB)
__global__ void __launch_bounds__(192) agg_kernel(int inbuf, int outbuf,
                           const float* __restrict__ ef_table,
                           const float* __restrict__ time_w, const float* __restrict__ time_b,
                           float* __restrict__ out, int last) {
    int etype = (blockIdx.x >= AGG_GB) ? 1 : 0;
    int blk = blockIdx.x - etype * AGG_GB;

    __shared__ float sM0[1024], sM1[1024];
    __shared__ float sX[AGG_WARPS][1024];
    __shared__ float sF[AGG_WARPS][1024];
    for (int i = threadIdx.x; i < 1024; i += blockDim.x) {
        sM0[i] = g_M[etype][0][i];  sM1[i] = g_M[etype][1][i];
    }
    __syncthreads();

    int warp = threadIdx.x >> 5, lane = threadIdx.x & 31;
    int srctype = (etype == 0) ? 0 : 1;
    int dsttype = 1 - srctype;
    const float* hsrc = g_h[inbuf][srctype];
    const float* hdst = g_h[inbuf][dsttype];
    const int*   lsrc = g_lsrc[etype];
    const int*   leid = g_leid[etype];
    const float* lrt  = g_lrt[etype];
    const float* Tg0 = g_T[etype][0];
    const float* Tg1 = g_T[etype][1];
    const float* Eg0 = g_ET[etype][0];
    const float* Eg1 = g_ET[etype][1];
    float tw = time_w[lane], tb = time_b[lane];
    float sbr0 = g_bT[etype][0][lane], sbr1 = g_bT[etype][1][lane];
    float* X  = sX[warp];
    float* Fe = sF[warp];
    unsigned int xbase = (unsigned int)__cvta_generic_to_shared(X);
    unsigned int fbase = (unsigned int)__cvta_generic_to_shared(Fe);

    int rsub  = lane >> 3;
    int chunk = lane & 7;
    int laneSw = lane & 7;
    int laneHi = lane >> 2, laneLo = lane & 3;

    for (int rep = 0; rep < AGG_NPW; rep++) {
        int n = blk * AGG_NPB + warp * AGG_NPW + rep;
        if (n >= NBn) break;                        // warp-uniform

        float hd = hdst[n * DD + lane];
        // fused qt: qt_h = h_dst @ M_h
        float qt0 = 0.f, qt1 = 0.f;
        #pragma unroll
        for (int d = 0; d < 32; d++) {
            float hv = __shfl_sync(FULL, hd, d);
            qt0 = fmaf(hv, sM0[d * 32 + lane], qt0);
            qt1 = fmaf(hv, sM1[d * 32 + lane], qt1);
        }
        int beg = g_off[etype][n], deg = g_deg[etype][n];

        float u0 = 0.f, u1 = 0.f, e0 = 0.f, e1 = 0.f, den0 = 0.f, den1 = 0.f;
        float m0 = -1e30f, m1 = -1e30f;

        for (int base = 0; base < deg; base += 32) {
            int cnt = min(32, deg - base);
            int idx = beg + base + lane;
            bool valid = lane < cnt;
            int psrc = 0, peid = 0; float prt = 0.f;
            if (valid) { psrc = lsrc[idx]; peid = leid[idx]; prt = lrt[idx]; }

            for (int g = 0; g * 4 < cnt; g++) {
                int j = g * 4 + rsub;
                int srcj = __shfl_sync(FULL, psrc, j);
                int eidj = __shfl_sync(FULL, peid, j);
                cp_async16(xbase + (unsigned)(j * 128 + (((chunk ^ (j & 7)) << 4))),
                           hsrc + (size_t)srcj * DD + chunk * 4);
                cp_async16(fbase + (unsigned)(j * 128 + (chunk << 4)),
                           ef_table + (size_t)eidj * DD + chunk * 4);
            }
            cp_commit();
            cp_wait0();
            __syncwarp();

            float a0 = 0.f, a1 = 0.f;
            #pragma unroll
            for (int d = 0; d < 32; d++) {
                float xd = X[lane * 32 + ((((d >> 2) ^ laneSw) << 2) | (d & 3))];
                a0 = fmaf(xd, __shfl_sync(FULL, qt0, d), a0);
                a1 = fmaf(xd, __shfl_sync(FULL, qt1, d), a1);
            }
            float s0 = valid ? a0 * 0.25f : -1e30f;
            float s1 = valid ? a1 * 0.25f : -1e30f;

            float bm0 = s0, bm1 = s1;
            #pragma unroll
            for (int o = 16; o > 0; o >>= 1) {
                bm0 = fmaxf(bm0, __shfl_xor_sync(FULL, bm0, o));
                bm1 = fmaxf(bm1, __shfl_xor_sync(FULL, bm1, o));
            }
            float nm0 = fmaxf(m0, bm0), nm1 = fmaxf(m1, bm1);
            float sc0 = __expf(m0 - nm0), sc1 = __expf(m1 - nm1);
            u0 *= sc0; e0 *= sc0; den0 *= sc0; m0 = nm0;
            u1 *= sc1; e1 *= sc1; den1 *= sc1; m1 = nm1;
            float p0 = valid ? __expf(s0 - m0) : 0.f;
            float p1 = valid ? __expf(s1 - m1) : 0.f;
            float d0 = p0, d1 = p1;
            #pragma unroll
            for (int o = 16; o > 0; o >>= 1) {
                d0 += __shfl_xor_sync(FULL, d0, o);
                d1 += __shfl_xor_sync(FULL, d1, o);
            }
            den0 += d0; den1 += d1;

            for (int j = 0; j < cnt; j++) {
                float pj0 = __shfl_sync(FULL, p0, j);
                float pj1 = __shfl_sync(FULL, p1, j);
                float rt  = __shfl_sync(FULL, prt, j);
                float x = X[j * 32 + (((laneHi ^ (j & 7)) << 2) | laneLo)]
                          + __cosf(fmaf(rt, tw, tb));
                float fe = Fe[j * 32 + lane];
                u0 = fmaf(pj0, x, u0); u1 = fmaf(pj1, x, u1);
                e0 = fmaf(pj0, fe, e0); e1 = fmaf(pj1, fe, e1);
            }
            __syncwarp();
        }

        float inv0 = 1.f / (den0 + 1e-9f), inv1 = 1.f / (den1 + 1e-9f);
        float bs0 = den0 * inv0, bs1 = den1 * inv1;
        float xa0 = u0 * inv0, xa1 = u1 * inv1, ga0 = e0 * inv0, ga1 = e1 * inv1;

        float acc = bs0 * sbr0 + bs1 * sbr1;
        #pragma unroll
        for (int d = 0; d < 32; d++) {
            float a0 = __shfl_sync(FULL, xa0, d);
            float a1 = __shfl_sync(FULL, xa1, d);
            float b0 = __shfl_sync(FULL, ga0, d);
            float b1 = __shfl_sync(FULL, ga1, d);
            acc = fmaf(a0, __ldg(Tg0 + d * 32 + lane), acc);
            acc = fmaf(a1, __ldg(Tg1 + d * 32 + lane), acc);
            acc = fmaf(b0, __ldg(Eg0 + d * 32 + lane), acc);
            acc = fmaf(b1, __ldg(Eg1 + d * 32 + lane), acc);
        }
        float r = fmaxf(acc, 0.f) + hd;
        g_h[outbuf][dsttype][n * DD + lane] = r;
        if (last) out[(size_t)dsttype * NBD + n * DD + lane] = r;
    }
}

// ---------------- launch ----------------
extern "C" void kernel_launch(void* const* d_in, const int* in_sizes, int n_in,
                              void* d_out, int out_size) {
    const float* mem_a   = (const float*)d_in[0];
    const float* mem_p   = (const float*)d_in[1];
    const float* ef      = (const float*)d_in[2];
    const int*   nxa     = (const int*)  d_in[3];
    const int*   nxp     = (const int*)  d_in[4];
    const float* tsa     = (const float*)d_in[5];
    const float* tsp     = (const float*)d_in[6];
    const int*   ei_w    = (const int*)  d_in[7];
    const float* rt_w    = (const float*)d_in[8];
    const int*   eidx_w  = (const int*)  d_in[9];
    const int*   mask_w  = (const int*)  d_in[10];
    const int*   ei_r    = (const int*)  d_in[11];
    const float* rt_r    = (const float*)d_in[12];
    const int*   eidx_r  = (const int*)  d_in[13];
    const int*   mask_r  = (const int*)  d_in[14];
    const float* tw      = (const float*)d_in[15];
    const float* tb      = (const float*)d_in[16];
    const float* Wk_w    = (const float*)d_in[17];
    const float* Wq_w    = (const float*)d_in[18];
    const float* Wv_w    = (const float*)d_in[19];
    const float* elw_w   = (const float*)d_in[20];
    const float* elb_w   = (const float*)d_in[21];
    const float* Wk_r    = (const float*)d_in[22];
    const float* Wq_r    = (const float*)d_in[23];
    const float* Wv_r    = (const float*)d_in[24];
    const float* elw_r   = (const float*)d_in[25];
    const float* elb_r   = (const float*)d_in[26];
    const float* lin_a   = (const float*)d_in[27];
    const float* lin_p   = (const float*)d_in[28];
    float* out = (float*)d_out;

    int egrid = (NE + 255) / 256;
    zero_kernel<<<(NBn + 255) / 256, 256>>>();                                      // 0
    hist_kernel<<<egrid, 256>>>(ei_w + NE, mask_w, ei_r + NE, mask_r);              // 1
    offs_kernel<<<dim3((NBn + 255) / 256, 2), 256>>>();                             // 2
    fill_kernel<<<egrid, 256>>>(ei_w, eidx_w, rt_w, mask_w, ei_r, eidx_r, rt_r, mask_r); // 3
    prep_kernel<<<INIT_B + 1, 256>>>(mem_a, mem_p, nxa, nxp, tsa, tsp, tw, tb,
                                     Wq_w, Wk_w, Wq_r, Wk_r,
                                     Wv_w, lin_p, Wv_r, lin_a,
                                     elw_w, elb_w, elw_r, elb_r, out);              // 4
    agg_kernel<<<2 * AGG_GB, 192>>>(0, 1, ef, tw, tb, out, 0);                      // 5 <- ncu
    agg_kernel<<<2 * AGG_GB, 192>>>(1, 0, ef, tw, tb, out, 1);                      // 6
}

// round 17
// speedup vs baseline: 1.8322x; 1.0255x over previous
#include <cuda_runtime.h>
#include <cstdint>
#include <math.h>

#define NBn 100000
#define NE  2000000
#define DD  32
#define NBD (NBn*DD)
#define FULL 0xffffffffu

// ---------------- device scratch (static, no runtime alloc) ----------------
__device__ float g_h[2][2][NBD];     // [buf][type: 0=author,1=paper]
__device__ int   g_deg[2][NBn];
__device__ int   g_off[2][NBn];
__device__ int   g_cur[2][NBn];
__device__ int4  g_edge[2][NE];      // packed CSR payload: {src, eid, rt_bits, 0}
__device__ int   g_gcnt[2];
__device__ float g_M [2][2][1024];   // [etype][head] Wq_h @ Wk_h^T
__device__ float g_T [2][2][1024];   // [etype][head][d*32+j]  Wv_h @ lin_h
__device__ float g_ET[2][2][1024];   // elin_w @ T
__device__ float g_bT[2][2][32];     // elin_b @ T

__device__ __forceinline__ void cp_async16(unsigned int saddr, const void* gptr) {
    asm volatile("cp.async.cg.shared.global [%0], [%1], 16;" :: "r"(saddr), "l"(gptr));
}
__device__ __forceinline__ void cp_commit() { asm volatile("cp.async.commit_group;"); }
__device__ __forceinline__ void cp_wait0()  { asm volatile("cp.async.wait_group 0;"); }

// ---------------- zero counters ----------------
__global__ void __launch_bounds__(256) zero_kernel() {
    int i = blockIdx.x * blockDim.x + threadIdx.x;
    if (i < NBn) {
        g_deg[0][i] = 0; g_deg[1][i] = 0;
        g_cur[0][i] = 0; g_cur[1][i] = 0;
    }
    if (i == 0) { g_gcnt[0] = 0; g_gcnt[1] = 0; }
}

// ---------------- CSR build ----------------
__global__ void __launch_bounds__(256) hist_kernel(const int* __restrict__ ei1_w,
                                                   const int* __restrict__ mask_w,
                                                   const int* __restrict__ ei1_r,
                                                   const int* __restrict__ mask_r) {
    int e = blockIdx.x * blockDim.x + threadIdx.x;
    if (e >= NE) return;
    if (mask_w[e] != 0) atomicAdd(&g_deg[0][ei1_w[e]], 1);
    if (mask_r[e] != 0) atomicAdd(&g_deg[1][ei1_r[e]], 1);
}

__global__ void __launch_bounds__(256) offs_kernel() {
    int etype = blockIdx.y;
    int n = blockIdx.x * blockDim.x + threadIdx.x;
    int lane = threadIdx.x & 31;
    int d = (n < NBn) ? g_deg[etype][n] : 0;
    int s = d;
    #pragma unroll
    for (int o = 1; o < 32; o <<= 1) {
        int t = __shfl_up_sync(FULL, s, o);
        if (lane >= o) s += t;
    }
    int tot = __shfl_sync(FULL, s, 31);
    int base = 0;
    if (lane == 31) base = atomicAdd(&g_gcnt[etype], tot);
    base = __shfl_sync(FULL, base, 31);
    if (n < NBn) g_off[etype][n] = base + s - d;
}

__global__ void __launch_bounds__(256) fill_kernel(
                            const int* __restrict__ ei_w, const int* __restrict__ eidx_w,
                            const float* __restrict__ rt_w, const int* __restrict__ mask_w,
                            const int* __restrict__ ei_r, const int* __restrict__ eidx_r,
                            const float* __restrict__ rt_r, const int* __restrict__ mask_r) {
    int e = blockIdx.x * blockDim.x + threadIdx.x;
    if (e >= NE) return;
    if (mask_w[e] != 0) {
        int dn = ei_w[NE + e];
        int pos = g_off[0][dn] + atomicAdd(&g_cur[0][dn], 1);
        g_edge[0][pos] = make_int4(ei_w[e], eidx_w[e], __float_as_int(rt_w[e]), 0);
    }
    if (mask_r[e] != 0) {
        int dn = ei_r[NE + e];
        int pos = g_off[1][dn] + atomicAdd(&g_cur[1][dn], 1);
        g_edge[1][pos] = make_int4(ei_r[e], eidx_r[e], __float_as_int(rt_r[e]), 0);
    }
}

// ---------------- prep: init h (+mem out) in blocks 0..INIT_B-1; weight folding in last block
#define INIT_B ((2*NBD + 255) / 256)
__global__ void __launch_bounds__(256) prep_kernel(
                            const float* __restrict__ mem_a, const float* __restrict__ mem_p,
                            const int* __restrict__ nxa, const int* __restrict__ nxp,
                            const float* __restrict__ tsa, const float* __restrict__ tsp,
                            const float* __restrict__ tw, const float* __restrict__ tb,
                            const float* __restrict__ Wq_w, const float* __restrict__ Wk_w,
                            const float* __restrict__ Wq_r, const float* __restrict__ Wk_r,
                            const float* __restrict__ Wv_w, const float* __restrict__ lin_p,
                            const float* __restrict__ Wv_r, const float* __restrict__ lin_a,
                            const float* __restrict__ elw_w, const float* __restrict__ elb_w,
                            const float* __restrict__ elw_r, const float* __restrict__ elb_r,
                            float* __restrict__ out) {
    if (blockIdx.x < INIT_B) {
        int i = blockIdx.x * 256 + threadIdx.x;
        if (i >= 2 * NBD) return;
        if (i < NBD) {
            int n = i >> 5, d = i & 31;
            float m = mem_a[(size_t)nxa[n] * DD + d];
            float te = __cosf(fmaf(tsa[n], tw[d], tb[d]));
            g_h[0][0][i] = m + te;
            out[(size_t)2 * NBD + i] = m;
        } else {
            int j = i - NBD;
            int n = j >> 5, d = j & 31;
            float m = mem_p[(size_t)nxp[n] * DD + d];
            float te = __cosf(fmaf(tsp[n], tw[d], tb[d]));
            g_h[0][1][j] = m + te;
            out[(size_t)3 * NBD + j] = m;
        }
        return;
    }
    // ---- const block: M, T, ET, bT ----
    __shared__ float sT[4096];
    int tid = threadIdx.x;
    for (int it = tid; it < 4096; it += 256) {    // M = Wq_h @ Wk_h^T
        int etype = it >> 11, head = (it >> 10) & 1, f = (it >> 5) & 31, g = it & 31;
        const float* Wq = etype ? Wq_r : Wq_w;
        const float* Wk = etype ? Wk_r : Wk_w;
        float acc = 0.f;
        #pragma unroll
        for (int m = 0; m < 16; m++)
            acc += Wq[f * 32 + head * 16 + m] * Wk[g * 32 + head * 16 + m];
        g_M[etype][head][f * 32 + g] = acc;
    }
    for (int it = tid; it < 4096; it += 256) {    // T = Wv_h @ lin
        int t = it >> 11, h = (it >> 10) & 1, d = (it >> 5) & 31, j = it & 31;
        const float* Wv  = t ? Wv_r  : Wv_w;
        const float* lin = t ? lin_a : lin_p;
        float acc = 0.f;
        #pragma unroll
        for (int m = 0; m < 16; m++)
            acc += Wv[d * 32 + h * 16 + m] * lin[(h * 16 + m) * 32 + j];
        sT[it] = acc;
        g_T[t][h][d * 32 + j] = acc;
    }
    __syncthreads();
    for (int it = tid; it < 4096; it += 256) {    // ET = elw @ T
        int t = it >> 11, h = (it >> 10) & 1, d = (it >> 5) & 31, j = it & 31;
        const float* elw = t ? elw_r : elw_w;
        const float* Tb = sT + t * 2048 + h * 1024;
        float acc = 0.f;
        #pragma unroll
        for (int k = 0; k < 32; k++)
            acc += elw[d * 32 + k] * Tb[k * 32 + j];
        g_ET[t][h][d * 32 + j] = acc;
    }
    for (int it = tid; it < 128; it += 256) {     // bT = elb @ T
        int t = it >> 6, h = (it >> 5) & 1, j = it & 31;
        const float* elb = t ? elb_r : elb_w;
        const float* Tb = sT + t * 2048 + h * 1024;
        float acc = 0.f;
        #pragma unroll
        for (int k = 0; k < 32; k++)
            acc += elb[k] * Tb[k * 32 + j];
        g_bT[t][h][j] = acc;
    }
}

// ---------------- attention aggregation + fused qt + node update ----------------
// 192 threads = 6 warps; each warp processes 8 nodes.
// X tile: row j stride 32; element d at j*32 + ((((d>>2)^(j&7))<<2)|(d&3)).
// F tile: plain [j][lane]. Epilogue weights via __ldg (L1-resident).
#define AGG_WARPS 6
#define AGG_NPW   8
#define AGG_NPB   (AGG_WARPS*AGG_NPW)
#define AGG_GB    ((NBn + AGG_NPB - 1) / AGG_NPB)
__global__ void __launch_bounds__(192) agg_kernel(int inbuf, int outbuf,
                           const float* __restrict__ ef_table,
                           const float* __restrict__ time_w, const float* __restrict__ time_b,
                           float* __restrict__ out, int last) {
    int etype = (blockIdx.x >= AGG_GB) ? 1 : 0;
    int blk = blockIdx.x - etype * AGG_GB;

    __shared__ float sM0[1024], sM1[1024];
    __shared__ float sX[AGG_WARPS][1024];
    __shared__ float sF[AGG_WARPS][1024];
    for (int i = threadIdx.x; i < 1024; i += blockDim.x) {
        sM0[i] = g_M[etype][0][i];  sM1[i] = g_M[etype][1][i];
    }
    __syncthreads();

    int warp = threadIdx.x >> 5, lane = threadIdx.x & 31;
    int srctype = (etype == 0) ? 0 : 1;
    int dsttype = 1 - srctype;
    const float* hsrc = g_h[inbuf][srctype];
    const float* hdst = g_h[inbuf][dsttype];
    const int4*  ledge = g_edge[etype];
    const float* Tg0 = g_T[etype][0];
    const float* Tg1 = g_T[etype][1];
    const float* Eg0 = g_ET[etype][0];
    const float* Eg1 = g_ET[etype][1];
    float tw = time_w[lane], tb = time_b[lane];
    float sbr0 = g_bT[etype][0][lane], sbr1 = g_bT[etype][1][lane];
    float* X  = sX[warp];
    float* Fe = sF[warp];
    unsigned int xbase = (unsigned int)__cvta_generic_to_shared(X);
    unsigned int fbase = (unsigned int)__cvta_generic_to_shared(Fe);

    int rsub  = lane >> 3;
    int chunk = lane & 7;
    int laneSw = lane & 7;
    int laneHi = lane >> 2, laneLo = lane & 3;

    for (int rep = 0; rep < AGG_NPW; rep++) {
        int n = blk * AGG_NPB + warp * AGG_NPW + rep;
        if (n >= NBn) break;                        // warp-uniform

        float hd = hdst[n * DD + lane];
        // fused qt: qt_h = h_dst @ M_h
        float qt0 = 0.f, qt1 = 0.f;
        #pragma unroll
        for (int d = 0; d < 32; d++) {
            float hv = __shfl_sync(FULL, hd, d);
            qt0 = fmaf(hv, sM0[d * 32 + lane], qt0);
            qt1 = fmaf(hv, sM1[d * 32 + lane], qt1);
        }
        int beg = g_off[etype][n], deg = g_deg[etype][n];

        float u0 = 0.f, u1 = 0.f, e0 = 0.f, e1 = 0.f, den0 = 0.f, den1 = 0.f;
        float m0 = -1e30f, m1 = -1e30f;

        for (int base = 0; base < deg; base += 32) {
            int cnt = min(32, deg - base);
            int idx = beg + base + lane;
            bool valid = lane < cnt;
            int psrc = 0, peid = 0; float prt = 0.f;
            if (valid) {
                int4 v = ledge[idx];
                psrc = v.x; peid = v.y; prt = __int_as_float(v.z);
            }

            for (int g = 0; g * 4 < cnt; g++) {
                int j = g * 4 + rsub;
                int srcj = __shfl_sync(FULL, psrc, j);
                int eidj = __shfl_sync(FULL, peid, j);
                cp_async16(xbase + (unsigned)(j * 128 + (((chunk ^ (j & 7)) << 4))),
                           hsrc + (size_t)srcj * DD + chunk * 4);
                cp_async16(fbase + (unsigned)(j * 128 + (chunk << 4)),
                           ef_table + (size_t)eidj * DD + chunk * 4);
            }
            cp_commit();
            cp_wait0();
            __syncwarp();

            float a0 = 0.f, a1 = 0.f;
            #pragma unroll
            for (int d = 0; d < 32; d++) {
                float xd = X[lane * 32 + ((((d >> 2) ^ laneSw) << 2) | (d & 3))];
                a0 = fmaf(xd, __shfl_sync(FULL, qt0, d), a0);
                a1 = fmaf(xd, __shfl_sync(FULL, qt1, d), a1);
            }
            float s0 = valid ? a0 * 0.25f : -1e30f;
            float s1 = valid ? a1 * 0.25f : -1e30f;

            float bm0 = s0, bm1 = s1;
            #pragma unroll
            for (int o = 16; o > 0; o >>= 1) {
                bm0 = fmaxf(bm0, __shfl_xor_sync(FULL, bm0, o));
                bm1 = fmaxf(bm1, __shfl_xor_sync(FULL, bm1, o));
            }
            float nm0 = fmaxf(m0, bm0), nm1 = fmaxf(m1, bm1);
            float sc0 = __expf(m0 - nm0), sc1 = __expf(m1 - nm1);
            u0 *= sc0; e0 *= sc0; den0 *= sc0; m0 = nm0;
            u1 *= sc1; e1 *= sc1; den1 *= sc1; m1 = nm1;
            float p0 = valid ? __expf(s0 - m0) : 0.f;
            float p1 = valid ? __expf(s1 - m1) : 0.f;
            float d0 = p0, d1 = p1;
            #pragma unroll
            for (int o = 16; o > 0; o >>= 1) {
                d0 += __shfl_xor_sync(FULL, d0, o);
                d1 += __shfl_xor_sync(FULL, d1, o);
            }
            den0 += d0; den1 += d1;

            for (int j = 0; j < cnt; j++) {
                float pj0 = __shfl_sync(FULL, p0, j);
                float pj1 = __shfl_sync(FULL, p1, j);
                float rt  = __shfl_sync(FULL, prt, j);
                float x = X[j * 32 + (((laneHi ^ (j & 7)) << 2) | laneLo)]
                          + __cosf(fmaf(rt, tw, tb));
                float fe = Fe[j * 32 + lane];
                u0 = fmaf(pj0, x, u0); u1 = fmaf(pj1, x, u1);
                e0 = fmaf(pj0, fe, e0); e1 = fmaf(pj1, fe, e1);
            }
            __syncwarp();
        }

        float inv0 = 1.f / (den0 + 1e-9f), inv1 = 1.f / (den1 + 1e-9f);
        float bs0 = den0 * inv0, bs1 = den1 * inv1;
        float xa0 = u0 * inv0, xa1 = u1 * inv1, ga0 = e0 * inv0, ga1 = e1 * inv1;

        float acc = bs0 * sbr0 + bs1 * sbr1;
        #pragma unroll
        for (int d = 0; d < 32; d++) {
            float a0 = __shfl_sync(FULL, xa0, d);
            float a1 = __shfl_sync(FULL, xa1, d);
            float b0 = __shfl_sync(FULL, ga0, d);
            float b1 = __shfl_sync(FULL, ga1, d);
            acc = fmaf(a0, __ldg(Tg0 + d * 32 + lane), acc);
            acc = fmaf(a1, __ldg(Tg1 + d * 32 + lane), acc);
            acc = fmaf(b0, __ldg(Eg0 + d * 32 + lane), acc);
            acc = fmaf(b1, __ldg(Eg1 + d * 32 + lane), acc);
        }
        float r = fmaxf(acc, 0.f) + hd;
        g_h[outbuf][dsttype][n * DD + lane] = r;
        if (last) out[(size_t)dsttype * NBD + n * DD + lane] = r;
    }
}

// ---------------- launch ----------------
extern "C" void kernel_launch(void* const* d_in, const int* in_sizes, int n_in,
                              void* d_out, int out_size) {
    const float* mem_a   = (const float*)d_in[0];
    const float* mem_p   = (const float*)d_in[1];
    const float* ef      = (const float*)d_in[2];
    const int*   nxa     = (const int*)  d_in[3];
    const int*   nxp     = (const int*)  d_in[4];
    const float* tsa     = (const float*)d_in[5];
    const float* tsp     = (const float*)d_in[6];
    const int*   ei_w    = (const int*)  d_in[7];
    const float* rt_w    = (const float*)d_in[8];
    const int*   eidx_w  = (const int*)  d_in[9];
    const int*   mask_w  = (const int*)  d_in[10];
    const int*   ei_r    = (const int*)  d_in[11];
    const float* rt_r    = (const float*)d_in[12];
    const int*   eidx_r  = (const int*)  d_in[13];
    const int*   mask_r  = (const int*)  d_in[14];
    const float* tw      = (const float*)d_in[15];
    const float* tb      = (const float*)d_in[16];
    const float* Wk_w    = (const float*)d_in[17];
    const float* Wq_w    = (const float*)d_in[18];
    const float* Wv_w    = (const float*)d_in[19];
    const float* elw_w   = (const float*)d_in[20];
    const float* elb_w   = (const float*)d_in[21];
    const float* Wk_r    = (const float*)d_in[22];
    const float* Wq_r    = (const float*)d_in[23];
    const float* Wv_r    = (const float*)d_in[24];
    const float* elw_r   = (const float*)d_in[25];
    const float* elb_r   = (const float*)d_in[26];
    const float* lin_a   = (const float*)d_in[27];
    const float* lin_p   = (const float*)d_in[28];
    float* out = (float*)d_out;

    int egrid = (NE + 255) / 256;
    zero_kernel<<<(NBn + 255) / 256, 256>>>();                                      // 0
    hist_kernel<<<egrid, 256>>>(ei_w + NE, mask_w, ei_r + NE, mask_r);              // 1
    offs_kernel<<<dim3((NBn + 255) / 256, 2), 256>>>();                             // 2
    fill_kernel<<<egrid, 256>>>(ei_w, eidx_w, rt_w, mask_w, ei_r, eidx_r, rt_r, mask_r); // 3
    prep_kernel<<<INIT_B + 1, 256>>>(mem_a, mem_p, nxa, nxp, tsa, tsp, tw, tb,
                                     Wq_w, Wk_w, Wq_r, Wk_r,
                                     Wv_w, lin_p, Wv_r, lin_a,
                                     elw_w, elb_w, elw_r, elb_r, out);              // 4
    agg_kernel<<<2 * AGG_GB, 192>>>(0, 1, ef, tw, tb, out, 0);                      // 5 <- ncu
    agg_kernel<<<2 * AGG_GB, 192>>>(1, 0, ef, tw, tb, out, 1);                      // 6
}